// round 14
// baseline (speedup 1.0000x reference)
#include <cuda_runtime.h>
#include <cuda_fp16.h>
#include <cstdint>
#include <math.h>

// Problem constants
#define BATCH 4
#define SEQ   2048
#define DM    2048
#define NH    16
#define DH    128
#define RH    64
#define NTOK  (BATCH*SEQ)      // 8192
#define QKVN  (3*DM)           // 6144
#define BH    (BATCH*NH)       // 64

// ---------------- scratch (device globals) ----------------------------------
__device__ __half g_xhi[(size_t)NTOK*DM];
__device__ __half g_xlo[(size_t)NTOK*DM];
__device__ __half g_ahi[(size_t)NTOK*DM];
__device__ __half g_alo[(size_t)NTOK*DM];
__device__ __half g_wqkvT[(size_t)QKVN*DM];
__device__ __half g_woutT[(size_t)DM*DM];

// attention operands
__device__ __half g_qhi[(size_t)BH*SEQ*DH];
__device__ __half g_qlo[(size_t)BH*SEQ*DH];
__device__ __half g_k  [(size_t)BH*SEQ*DH];
__device__ __half g_v  [(size_t)BH*SEQ*DH];   // [bh, s, d]
__device__ __half g_vt [(size_t)BH*DH*SEQ];   // [bh, d, s]

// ---------------- PTX helpers -------------------------------------------------
__device__ __forceinline__ uint32_t smem_u32(const void* p) {
    uint32_t a;
    asm("{ .reg .u64 t; cvta.to.shared.u64 t, %1; cvt.u32.u64 %0, t; }" : "=r"(a) : "l"(p));
    return a;
}
#define CP_ASYNC16(dst, src) \
    asm volatile("cp.async.cg.shared.global [%0], [%1], 16;" :: "r"(dst), "l"(src))
#define CP_COMMIT() asm volatile("cp.async.commit_group;" ::: "memory")
#define CP_WAIT(n)  asm volatile("cp.async.wait_group %0;" :: "n"(n) : "memory")

__device__ __forceinline__ void ldsm_x4(uint32_t* r, uint32_t addr) {
    asm volatile("ldmatrix.sync.aligned.m8n8.x4.shared.b16 {%0,%1,%2,%3}, [%4];"
        : "=r"(r[0]), "=r"(r[1]), "=r"(r[2]), "=r"(r[3]) : "r"(addr));
}
__device__ __forceinline__ void mma_f16(float* d, const uint32_t* a,
                                        uint32_t b0, uint32_t b1) {
    asm volatile("mma.sync.aligned.m16n8k16.row.col.f32.f16.f16.f32 "
        "{%0,%1,%2,%3}, {%4,%5,%6,%7}, {%8,%9}, {%0,%1,%2,%3};"
        : "+f"(d[0]), "+f"(d[1]), "+f"(d[2]), "+f"(d[3])
        : "r"(a[0]), "r"(a[1]), "r"(a[2]), "r"(a[3]), "r"(b0), "r"(b1));
}
__device__ __forceinline__ void pack_hilo(float x, float y, uint32_t& hi, uint32_t& lo) {
    __half2 h = __floats2half2_rn(x, y);
    float rx = x - __half2float(__low2half(h));
    float ry = y - __half2float(__high2half(h));
    __half2 l = __floats2half2_rn(rx, ry);
    hi = *reinterpret_cast<uint32_t*>(&h);
    lo = *reinterpret_cast<uint32_t*>(&l);
}
__device__ __forceinline__ uint32_t pack_f16(float x, float y) {
    __half2 h = __floats2half2_rn(x, y);
    return *reinterpret_cast<uint32_t*>(&h);
}

// ---------------- split / transpose kernels ----------------------------------
__global__ void split_a(const float* __restrict__ in,
                        __half* __restrict__ hi, __half* __restrict__ lo, int n4)
{
    int i = blockIdx.x * blockDim.x + threadIdx.x;
    if (i >= n4) return;
    float4 v = ((const float4*)in)[i];
    uint32_t h0, l0, h1, l1;
    pack_hilo(v.x, v.y, h0, l0);
    pack_hilo(v.z, v.w, h1, l1);
    ((uint32_t*)hi)[i*2]   = h0;  ((uint32_t*)hi)[i*2+1] = h1;
    ((uint32_t*)lo)[i*2]   = l0;  ((uint32_t*)lo)[i*2+1] = l1;
}

// W[R,C] fp32 -> T[C,R] fp16 (single rounding)
__global__ void transpose_w(const float* __restrict__ W,
                            __half* __restrict__ T, int R, int C)
{
    __shared__ float t[32][33];
    int c0 = blockIdx.x * 32, r0 = blockIdx.y * 32;
    int tx = threadIdx.x, ty = threadIdx.y;
#pragma unroll
    for (int j = 0; j < 4; j++)
        t[ty + j*8][tx] = W[(size_t)(r0 + ty + j*8) * C + c0 + tx];
    __syncthreads();
#pragma unroll
    for (int j = 0; j < 4; j++) {
        int cc = c0 + ty + j*8;
        T[(size_t)cc * R + r0 + tx] = __float2half_rn(t[tx][ty + j*8]);
    }
}

// g_v [bh,s,d] fp16 -> g_vt [bh,d,s] fp16
__global__ void v_transpose_f16()
{
    __shared__ __half t[32][33];
    const int bh = blockIdx.z;
    const int d0 = blockIdx.x * 32, s0 = blockIdx.y * 32;
    const int tx = threadIdx.x, ty = threadIdx.y;
#pragma unroll
    for (int j = 0; j < 4; j++)
        t[ty + j*8][tx] = g_v[((size_t)bh * SEQ + s0 + ty + j*8) * DH + d0 + tx];
    __syncthreads();
#pragma unroll
    for (int j = 0; j < 4; j++)
        g_vt[((size_t)bh * DH + d0 + ty + j*8) * SEQ + s0 + tx] = t[tx][ty + j*8];
}

// ---------------- fp16x2 GEMM via mma.sync, 3 CTAs/SM ------------------------
#define TK 32
#define TILE_B (128*64)        // 8192
#define STAGE  (3*TILE_B)      // 24576: Ahi, Alo, B
#define GEMM_SMEM (3*STAGE)    // 73728

__device__ __forceinline__ uint32_t sw_off(int row, int c) {
    return (uint32_t)(row * 64 + ((c ^ ((row >> 1) & 3)) << 4));
}

__device__ __forceinline__ void gemm_load_stage(
    uint32_t st, const __half* Ahi, const __half* Alo, const __half* B,
    int bm, int bn, int kt, int K, int tid)
{
    const int rb = tid >> 2;
    const int c  = tid & 3;
#pragma unroll
    for (int q = 0; q < 4; q++) {
        const int r = q * 32 + rb;
        const uint32_t dso = sw_off(r, c);
        CP_ASYNC16(st + dso,              Ahi + (size_t)(bm + r) * K + kt + c * 8);
        CP_ASYNC16(st + TILE_B + dso,     Alo + (size_t)(bm + r) * K + kt + c * 8);
        CP_ASYNC16(st + 2 * TILE_B + dso, B   + (size_t)(bn + r) * K + kt + c * 8);
    }
}

template<int MODE>
__global__ __launch_bounds__(128, 3)
void gemm_tc(const __half* __restrict__ Ahi, const __half* __restrict__ Alo,
             const __half* __restrict__ B,
             const float* __restrict__ bias, float* __restrict__ C,
             const float* __restrict__ rc, const float* __restrict__ rs,
             int M, int N, int K)
{
    extern __shared__ char sm[];
    const uint32_t sbase = smem_u32(sm);

    const int tid = threadIdx.x;
    const int wid = tid >> 5;
    const int lane = tid & 31;
    const int warpM = wid >> 1;
    const int warpN = wid & 1;
    const int bn = blockIdx.x * 128;
    const int bm = blockIdx.y * 128;

    float acc[4][8][4];
#pragma unroll
    for (int mi = 0; mi < 4; mi++)
#pragma unroll
        for (int ni = 0; ni < 8; ni++)
#pragma unroll
            for (int r = 0; r < 4; r++) acc[mi][ni][r] = 0.f;

    const int NI = K / TK;

    gemm_load_stage(sbase,         Ahi, Alo, B, bm, bn, 0,  K, tid);
    CP_COMMIT();
    gemm_load_stage(sbase + STAGE, Ahi, Alo, B, bm, bn, TK, K, tid);
    CP_COMMIT();

    int buf = 0;
    for (int i = 0; i < NI; i++) {
        if (i + 1 < NI) { CP_WAIT(1); } else { CP_WAIT(0); }
        __syncthreads();

        if (i + 2 < NI) {
            int nb = buf + 2; if (nb >= 3) nb -= 3;
            gemm_load_stage(sbase + nb * STAGE, Ahi, Alo, B, bm, bn,
                            (i + 2) * TK, K, tid);
            CP_COMMIT();
        }

        const uint32_t st = sbase + buf * STAGE;
        const uint32_t Ah = st, Al = st + TILE_B, Bh = st + 2 * TILE_B;
        const int ar = warpM * 64 + (lane & 15);
        const int br = warpN * 64 + (lane & 15);

#pragma unroll
        for (int ks = 0; ks < 2; ks++) {
            const int cc = ks * 2 + (lane >> 4);
            const uint32_t aoff = sw_off(ar, cc);
            const uint32_t boff = sw_off(br, cc);

            uint32_t ahf[4][4], alf[4][4];
#pragma unroll
            for (int mi = 0; mi < 4; mi++) {
                ldsm_x4(ahf[mi], Ah + aoff + mi * 1024);
                ldsm_x4(alf[mi], Al + aoff + mi * 1024);
            }
#pragma unroll
            for (int np = 0; np < 4; np++) {
                uint32_t bhf[4];
                ldsm_x4(bhf, Bh + boff + np * 1024);
#pragma unroll
                for (int mi = 0; mi < 4; mi++)
#pragma unroll
                    for (int o = 0; o < 2; o++) {
                        const int ni = np * 2 + o;
                        mma_f16(acc[mi][ni], ahf[mi], bhf[o], bhf[o + 2]);
                        mma_f16(acc[mi][ni], alf[mi], bhf[o], bhf[o + 2]);
                    }
            }
        }
        buf++; if (buf >= 3) buf = 0;
    }

    if (MODE == 0) {
#pragma unroll
        for (int mi = 0; mi < 4; mi++) {
            const int r0 = bm + warpM * 64 + mi * 16 + (lane >> 2);
#pragma unroll
            for (int ni = 0; ni < 8; ni++) {
                const int c0 = bn + warpN * 64 + ni * 8 + (lane & 3) * 2;
                const float b0 = bias[c0], b1 = bias[c0 + 1];
                float2 v0 = make_float2(acc[mi][ni][0] + b0, acc[mi][ni][1] + b1);
                float2 v1 = make_float2(acc[mi][ni][2] + b0, acc[mi][ni][3] + b1);
                *(float2*)(C + (size_t)r0 * N + c0) = v0;
                *(float2*)(C + (size_t)(r0 + 8) * N + c0) = v1;
            }
        }
    } else {
        const int region = bn >> 11;               // 0=Q, 1=K, 2=V
        const int h = (bn >> 7) & (NH - 1);
#pragma unroll
        for (int mi = 0; mi < 4; mi++) {
            const int r0 = bm + warpM * 64 + mi * 16 + (lane >> 2);
            const int bb = r0 >> 11;
            const int s0 = r0 & (SEQ - 1);
            const int s1 = s0 + 8;
            const size_t bhs0 = ((size_t)(bb * NH + h) * SEQ + s0) * DH;
            const size_t bhs1 = bhs0 + (size_t)8 * DH;
#pragma unroll
            for (int ni = 0; ni < 8; ni++) {
                const int c = warpN * 64 + ni * 8 + (lane & 3) * 2;
                const float bi0 = bias[bn + c], bi1 = bias[bn + c + 1];
                const float e0 = acc[mi][ni][0] + bi0, o0 = acc[mi][ni][1] + bi1;
                const float e1 = acc[mi][ni][2] + bi0, o1 = acc[mi][ni][3] + bi1;
                const size_t i0 = (bhs0 + c) >> 1;
                const size_t i1 = (bhs1 + c) >> 1;
                if (region == 2) {
                    ((uint32_t*)g_v)[i0] = pack_f16(e0, o0);
                    ((uint32_t*)g_v)[i1] = pack_f16(e1, o1);
                } else {
                    const int j = c >> 1;
                    const float c0 = rc[s0 * RH + j], sn0 = rs[s0 * RH + j];
                    const float c1 = rc[s1 * RH + j], sn1 = rs[s1 * RH + j];
                    const float re0 = e0 * c0 - o0 * sn0, ro0 = e0 * sn0 + o0 * c0;
                    const float re1 = e1 * c1 - o1 * sn1, ro1 = e1 * sn1 + o1 * c1;
                    if (region == 0) {
                        uint32_t hi, lo;
                        pack_hilo(re0, ro0, hi, lo);
                        ((uint32_t*)g_qhi)[i0] = hi; ((uint32_t*)g_qlo)[i0] = lo;
                        pack_hilo(re1, ro1, hi, lo);
                        ((uint32_t*)g_qhi)[i1] = hi; ((uint32_t*)g_qlo)[i1] = lo;
                    } else {
                        ((uint32_t*)g_k)[i0] = pack_f16(re0, ro0);
                        ((uint32_t*)g_k)[i1] = pack_f16(re1, ro1);
                    }
                }
            }
        }
    }
}

// ---------------- fp16x2 HMMA flash attention, Q-tile 64, 2 CTAs/SM ----------
#define KSTR 272                 // 128 fp16 = 256B + 16 pad
#define VSTR 144                 // 64 fp16 = 128B + 16 pad
#define KTILE (64*KSTR)          // 17408
#define VTILE (128*VSTR)         // 18432
#define ASTAGE (KTILE + VTILE)   // 35840
#define QSTR 272
#define QTILE (64*QSTR)          // 17408
#define ATTN_SMEM (2*QTILE + 2*ASTAGE)  // 106496 -> 2 CTAs/SM

__device__ __forceinline__ void attn_load_kv(uint32_t st, int bh, int k0, int tid)
{
    {
        const int rb = tid >> 4, c = tid & 15;
#pragma unroll
        for (int q = 0; q < 8; q++) {
            const int r = q * 8 + rb;
            CP_ASYNC16(st + r * KSTR + c * 16,
                       g_k + ((size_t)bh * SEQ + k0 + r) * DH + c * 8);
        }
    }
    {
        const int rb = tid >> 3, c = tid & 7;
#pragma unroll
        for (int q = 0; q < 8; q++) {
            const int r = q * 16 + rb;
            CP_ASYNC16(st + KTILE + r * VSTR + c * 16,
                       g_vt + ((size_t)bh * DH + r) * SEQ + k0 + c * 8);
        }
    }
}

__global__ __launch_bounds__(128)
void attn_hmma()
{
    extern __shared__ char sm[];
    const uint32_t sbase = smem_u32(sm);
    const uint32_t qb_smem = sbase;
    const uint32_t stage0 = sbase + 2 * QTILE;

    const int qb = 31 - blockIdx.x;           // heavy tiles first
    const int h = blockIdx.y, b = blockIdx.z;
    const int bh = b * NH + h;
    const int q0 = qb * 64;
    const int tid = threadIdx.x;
    const int w = tid >> 5;
    const int lane = tid & 31;
    const float scale = 0.08838834764831845f;

    {
        const int rb = tid >> 4, c = tid & 15;
#pragma unroll
        for (int sec = 0; sec < 2; sec++)
#pragma unroll
            for (int q = 0; q < 8; q++) {
                const int r = q * 8 + rb;
                const size_t g = ((size_t)bh * SEQ + q0 + r) * DH + c * 8;
                CP_ASYNC16(qb_smem + sec * QTILE + r * QSTR + c * 16,
                           (sec ? g_qlo : g_qhi) + g);
            }
    }
    CP_COMMIT();
    CP_WAIT(0);
    __syncthreads();

    uint32_t qh[8][4], ql[8][4];
    {
        const uint32_t arow = (w * 16 + (lane & 15)) * QSTR + (lane >> 4) * 16;
#pragma unroll
        for (int kt = 0; kt < 8; kt++) {
            ldsm_x4(qh[kt], qb_smem + arow + kt * 32);
            ldsm_x4(ql[kt], qb_smem + QTILE + arow + kt * 32);
        }
    }

    float oa[16][4];
#pragma unroll
    for (int dt = 0; dt < 16; dt++)
#pragma unroll
        for (int r = 0; r < 4; r++) oa[dt][r] = 0.f;
    float m0 = -1e30f, m1 = -1e30f, l0 = 0.f, l1 = 0.f;

    const int nch = qb + 1;

    attn_load_kv(stage0, bh, 0, tid);
    CP_COMMIT();

    for (int kb = 0; kb < nch; kb++) {
        if (kb + 1 < nch) {
            attn_load_kv(stage0 + ((kb + 1) & 1) * ASTAGE, bh, (kb + 1) * 64, tid);
            CP_COMMIT();
            CP_WAIT(1);
        } else {
            CP_WAIT(0);
        }
        __syncthreads();

        const uint32_t st = stage0 + (kb & 1) * ASTAGE;
        const int k0 = kb * 64;

        float e[8][4];
#pragma unroll
        for (int nt = 0; nt < 8; nt++)
#pragma unroll
            for (int r = 0; r < 4; r++) e[nt][r] = 0.f;

#pragma unroll
        for (int kt = 0; kt < 8; kt++) {
            const uint32_t ko = kt * 32 + (lane >> 4) * 16;
#pragma unroll
            for (int np = 0; np < 4; np++) {
                const uint32_t brow = (np * 16 + (lane & 15)) * KSTR + ko;
                uint32_t bhf[4];
                ldsm_x4(bhf, st + brow);
#pragma unroll
                for (int o = 0; o < 2; o++) {
                    const int nt = 2 * np + o;
                    mma_f16(e[nt], qh[kt], bhf[o], bhf[o + 2]);
                    mma_f16(e[nt], ql[kt], bhf[o], bhf[o + 2]);
                }
            }
        }

#pragma unroll
        for (int nt = 0; nt < 8; nt++)
#pragma unroll
            for (int r = 0; r < 4; r++) e[nt][r] *= scale;

        const int row0 = q0 + w * 16 + (lane >> 2);
        if (kb == qb) {
#pragma unroll
            for (int nt = 0; nt < 8; nt++) {
                const int col = k0 + nt * 8 + (lane & 3) * 2;
                if (col     > row0)     e[nt][0] = -1e30f;
                if (col + 1 > row0)     e[nt][1] = -1e30f;
                if (col     > row0 + 8) e[nt][2] = -1e30f;
                if (col + 1 > row0 + 8) e[nt][3] = -1e30f;
            }
        }

        float rm0 = e[0][0], rm1 = e[0][2];
#pragma unroll
        for (int nt = 0; nt < 8; nt++) {
            rm0 = fmaxf(rm0, fmaxf(e[nt][0], e[nt][1]));
            rm1 = fmaxf(rm1, fmaxf(e[nt][2], e[nt][3]));
        }
        rm0 = fmaxf(rm0, __shfl_xor_sync(0xffffffffu, rm0, 1));
        rm0 = fmaxf(rm0, __shfl_xor_sync(0xffffffffu, rm0, 2));
        rm1 = fmaxf(rm1, __shfl_xor_sync(0xffffffffu, rm1, 1));
        rm1 = fmaxf(rm1, __shfl_xor_sync(0xffffffffu, rm1, 2));

        const float mn0 = fmaxf(m0, rm0), mn1 = fmaxf(m1, rm1);
        const float al0 = __expf(m0 - mn0), al1 = __expf(m1 - mn1);
        m0 = mn0; m1 = mn1;

        float s0 = 0.f, s1 = 0.f;
#pragma unroll
        for (int nt = 0; nt < 8; nt++) {
            e[nt][0] = __expf(e[nt][0] - mn0);
            e[nt][1] = __expf(e[nt][1] - mn0);
            e[nt][2] = __expf(e[nt][2] - mn1);
            e[nt][3] = __expf(e[nt][3] - mn1);
            s0 += e[nt][0] + e[nt][1];
            s1 += e[nt][2] + e[nt][3];
        }
        s0 += __shfl_xor_sync(0xffffffffu, s0, 1);
        s0 += __shfl_xor_sync(0xffffffffu, s0, 2);
        s1 += __shfl_xor_sync(0xffffffffu, s1, 1);
        s1 += __shfl_xor_sync(0xffffffffu, s1, 2);
        l0 = l0 * al0 + s0;
        l1 = l1 * al1 + s1;

#pragma unroll
        for (int dt = 0; dt < 16; dt++) {
            oa[dt][0] *= al0; oa[dt][1] *= al0;
            oa[dt][2] *= al1; oa[dt][3] *= al1;
        }

        const uint32_t vb = st + KTILE;
#pragma unroll
        for (int kt2 = 0; kt2 < 4; kt2++) {
            const int ta = 2 * kt2, tb = ta + 1;
            uint32_t ph[4], pl[4];
            pack_hilo(e[ta][0], e[ta][1], ph[0], pl[0]);
            pack_hilo(e[ta][2], e[ta][3], ph[1], pl[1]);
            pack_hilo(e[tb][0], e[tb][1], ph[2], pl[2]);
            pack_hilo(e[tb][2], e[tb][3], ph[3], pl[3]);

            const uint32_t ko = kt2 * 32 + (lane >> 4) * 16;
#pragma unroll
            for (int np = 0; np < 8; np++) {
                const uint32_t brow = (np * 16 + (lane & 15)) * VSTR + ko;
                uint32_t bhf[4];
                ldsm_x4(bhf, vb + brow);
#pragma unroll
                for (int o = 0; o < 2; o++) {
                    const int dt = 2 * np + o;
                    mma_f16(oa[dt], ph, bhf[o], bhf[o + 2]);
                    mma_f16(oa[dt], pl, bhf[o], bhf[o + 2]);
                }
            }
        }
        __syncthreads();
    }

    const float inv0 = 1.f / l0, inv1 = 1.f / l1;
    const size_t tokA = (size_t)b * SEQ + q0 + w * 16 + (lane >> 2);
    const size_t tokB = tokA + 8;
    const int colb = h * DH + (lane & 3) * 2;
    uint32_t* ahi = (uint32_t*)g_ahi;
    uint32_t* alo = (uint32_t*)g_alo;
#pragma unroll
    for (int dt = 0; dt < 16; dt++) {
        const int col = colb + dt * 8;
        uint32_t hi, lo;
        pack_hilo(oa[dt][0] * inv0, oa[dt][1] * inv0, hi, lo);
        ahi[(tokA * DM + col) >> 1] = hi;
        alo[(tokA * DM + col) >> 1] = lo;
        pack_hilo(oa[dt][2] * inv1, oa[dt][3] * inv1, hi, lo);
        ahi[(tokB * DM + col) >> 1] = hi;
        alo[(tokB * DM + col) >> 1] = lo;
    }
}

// ---------------- launch -----------------------------------------------------
extern "C" void kernel_launch(void* const* d_in, const int* in_sizes, int n_in,
                              void* d_out, int out_size)
{
    const float* x     = (const float*)d_in[0];
    const float* w_qkv = (const float*)d_in[1];
    const float* b_qkv = (const float*)d_in[2];
    const float* w_out = (const float*)d_in[3];
    const float* b_out = (const float*)d_in[4];
    const float* rc    = (const float*)d_in[5];
    const float* rs    = (const float*)d_in[6];
    float* out = (float*)d_out;

    __half *p_xhi, *p_xlo, *p_ahi, *p_alo, *p_wq, *p_wo;
    cudaGetSymbolAddress((void**)&p_xhi, g_xhi);
    cudaGetSymbolAddress((void**)&p_xlo, g_xlo);
    cudaGetSymbolAddress((void**)&p_ahi, g_ahi);
    cudaGetSymbolAddress((void**)&p_alo, g_alo);
    cudaGetSymbolAddress((void**)&p_wq, g_wqkvT);
    cudaGetSymbolAddress((void**)&p_wo, g_woutT);

    cudaFuncSetAttribute(gemm_tc<0>,
                         cudaFuncAttributeMaxDynamicSharedMemorySize, GEMM_SMEM);
    cudaFuncSetAttribute(gemm_tc<1>,
                         cudaFuncAttributeMaxDynamicSharedMemorySize, GEMM_SMEM);
    cudaFuncSetAttribute(attn_hmma,
                         cudaFuncAttributeMaxDynamicSharedMemorySize, ATTN_SMEM);

    // 1) split x -> fp16 hi/lo
    {
        int n4 = NTOK * DM / 4;
        split_a<<<(n4 + 255) / 256, 256>>>(x, p_xhi, p_xlo, n4);
    }
    // 2) transpose weights -> fp16
    transpose_w<<<dim3(QKVN / 32, DM / 32), dim3(32, 8)>>>(w_qkv, p_wq, DM, QKVN);
    transpose_w<<<dim3(DM / 32, DM / 32), dim3(32, 8)>>>(w_out, p_wo, DM, DM);
    // 3) fused QKV GEMM + bias + RoPE + fp16 split -> g_qhi/qlo, g_k, g_v
    gemm_tc<1><<<dim3(QKVN / 128, NTOK / 128), 128, GEMM_SMEM>>>(
        p_xhi, p_xlo, p_wq, b_qkv, nullptr, rc, rs, NTOK, QKVN, DM);
    // 4) V transpose (fp16 in/out) -> [bh,d,s]
    v_transpose_f16<<<dim3(DH / 32, SEQ / 32, BH), dim3(32, 8)>>>();
    // 5) fp16x2 HMMA flash attention, 64-row Q tiles, 2 CTAs/SM
    attn_hmma<<<dim3(SEQ / 64, NH, BATCH), 128, ATTN_SMEM>>>();
    // 6) out = att @ w_out + b  (fp16x2 HMMA)
    gemm_tc<0><<<dim3(DM / 128, NTOK / 128), 128, GEMM_SMEM>>>(
        p_ahi, p_alo, p_wo, b_out, out, nullptr, nullptr, NTOK, DM, DM);
}

// round 15
// speedup vs baseline: 1.1468x; 1.1468x over previous
#include <cuda_runtime.h>
#include <cuda_fp16.h>
#include <cstdint>
#include <math.h>

// Problem constants
#define BATCH 4
#define SEQ   2048
#define DM    2048
#define NH    16
#define DH    128
#define RH    64
#define NTOK  (BATCH*SEQ)      // 8192
#define QKVN  (3*DM)           // 6144
#define BH    (BATCH*NH)       // 64

// ---------------- scratch (device globals) ----------------------------------
__device__ __half g_xhi[(size_t)NTOK*DM];
__device__ __half g_xlo[(size_t)NTOK*DM];
__device__ __half g_ahi[(size_t)NTOK*DM];
__device__ __half g_alo[(size_t)NTOK*DM];
__device__ __half g_wqkvT[(size_t)QKVN*DM];
__device__ __half g_woutT[(size_t)DM*DM];

// attention operands
__device__ __half g_qhi[(size_t)BH*SEQ*DH];
__device__ __half g_qlo[(size_t)BH*SEQ*DH];
__device__ __half g_k  [(size_t)BH*SEQ*DH];
__device__ __half g_v  [(size_t)BH*SEQ*DH];   // [bh, s, d]
__device__ __half g_vt [(size_t)BH*DH*SEQ];   // [bh, d, s]

// ---------------- PTX helpers -------------------------------------------------
__device__ __forceinline__ uint32_t smem_u32(const void* p) {
    uint32_t a;
    asm("{ .reg .u64 t; cvta.to.shared.u64 t, %1; cvt.u32.u64 %0, t; }" : "=r"(a) : "l"(p));
    return a;
}
#define CP_ASYNC16(dst, src) \
    asm volatile("cp.async.cg.shared.global [%0], [%1], 16;" :: "r"(dst), "l"(src))
#define CP_COMMIT() asm volatile("cp.async.commit_group;" ::: "memory")
#define CP_WAIT(n)  asm volatile("cp.async.wait_group %0;" :: "n"(n) : "memory")

__device__ __forceinline__ void ldsm_x4(uint32_t* r, uint32_t addr) {
    asm volatile("ldmatrix.sync.aligned.m8n8.x4.shared.b16 {%0,%1,%2,%3}, [%4];"
        : "=r"(r[0]), "=r"(r[1]), "=r"(r[2]), "=r"(r[3]) : "r"(addr));
}
__device__ __forceinline__ void mma_f16(float* d, const uint32_t* a,
                                        uint32_t b0, uint32_t b1) {
    asm volatile("mma.sync.aligned.m16n8k16.row.col.f32.f16.f16.f32 "
        "{%0,%1,%2,%3}, {%4,%5,%6,%7}, {%8,%9}, {%0,%1,%2,%3};"
        : "+f"(d[0]), "+f"(d[1]), "+f"(d[2]), "+f"(d[3])
        : "r"(a[0]), "r"(a[1]), "r"(a[2]), "r"(a[3]), "r"(b0), "r"(b1));
}
__device__ __forceinline__ void pack_hilo(float x, float y, uint32_t& hi, uint32_t& lo) {
    __half2 h = __floats2half2_rn(x, y);
    float rx = x - __half2float(__low2half(h));
    float ry = y - __half2float(__high2half(h));
    __half2 l = __floats2half2_rn(rx, ry);
    hi = *reinterpret_cast<uint32_t*>(&h);
    lo = *reinterpret_cast<uint32_t*>(&l);
}
__device__ __forceinline__ uint32_t pack_f16(float x, float y) {
    __half2 h = __floats2half2_rn(x, y);
    return *reinterpret_cast<uint32_t*>(&h);
}

// ---------------- split / transpose kernels ----------------------------------
__global__ void split_a(const float* __restrict__ in,
                        __half* __restrict__ hi, __half* __restrict__ lo, int n4)
{
    int i = blockIdx.x * blockDim.x + threadIdx.x;
    if (i >= n4) return;
    float4 v = ((const float4*)in)[i];
    uint32_t h0, l0, h1, l1;
    pack_hilo(v.x, v.y, h0, l0);
    pack_hilo(v.z, v.w, h1, l1);
    ((uint32_t*)hi)[i*2]   = h0;  ((uint32_t*)hi)[i*2+1] = h1;
    ((uint32_t*)lo)[i*2]   = l0;  ((uint32_t*)lo)[i*2+1] = l1;
}

// W[R,C] fp32 -> T[C,R] fp16 (single rounding)
__global__ void transpose_w(const float* __restrict__ W,
                            __half* __restrict__ T, int R, int C)
{
    __shared__ float t[32][33];
    int c0 = blockIdx.x * 32, r0 = blockIdx.y * 32;
    int tx = threadIdx.x, ty = threadIdx.y;
#pragma unroll
    for (int j = 0; j < 4; j++)
        t[ty + j*8][tx] = W[(size_t)(r0 + ty + j*8) * C + c0 + tx];
    __syncthreads();
#pragma unroll
    for (int j = 0; j < 4; j++) {
        int cc = c0 + ty + j*8;
        T[(size_t)cc * R + r0 + tx] = __float2half_rn(t[tx][ty + j*8]);
    }
}

// g_v [bh,s,d] fp16 -> g_vt [bh,d,s] fp16
__global__ void v_transpose_f16()
{
    __shared__ __half t[32][33];
    const int bh = blockIdx.z;
    const int d0 = blockIdx.x * 32, s0 = blockIdx.y * 32;
    const int tx = threadIdx.x, ty = threadIdx.y;
#pragma unroll
    for (int j = 0; j < 4; j++)
        t[ty + j*8][tx] = g_v[((size_t)bh * SEQ + s0 + ty + j*8) * DH + d0 + tx];
    __syncthreads();
#pragma unroll
    for (int j = 0; j < 4; j++)
        g_vt[((size_t)bh * DH + d0 + ty + j*8) * SEQ + s0 + tx] = t[tx][ty + j*8];
}

// ---------------- fp16x2 GEMM via mma.sync (R11 config, no CTA bound) --------
#define TK 32
#define TILE_B (128*64)        // 8192
#define STAGE  (3*TILE_B)      // 24576: Ahi, Alo, B
#define GEMM_SMEM (3*STAGE)    // 73728

__device__ __forceinline__ uint32_t sw_off(int row, int c) {
    return (uint32_t)(row * 64 + ((c ^ ((row >> 1) & 3)) << 4));
}

__device__ __forceinline__ void gemm_load_stage(
    uint32_t st, const __half* Ahi, const __half* Alo, const __half* B,
    int bm, int bn, int kt, int K, int tid)
{
    const int rb = tid >> 2;
    const int c  = tid & 3;
#pragma unroll
    for (int q = 0; q < 4; q++) {
        const int r = q * 32 + rb;
        const uint32_t dso = sw_off(r, c);
        CP_ASYNC16(st + dso,              Ahi + (size_t)(bm + r) * K + kt + c * 8);
        CP_ASYNC16(st + TILE_B + dso,     Alo + (size_t)(bm + r) * K + kt + c * 8);
        CP_ASYNC16(st + 2 * TILE_B + dso, B   + (size_t)(bn + r) * K + kt + c * 8);
    }
}

template<int MODE>
__global__ __launch_bounds__(128)
void gemm_tc(const __half* __restrict__ Ahi, const __half* __restrict__ Alo,
             const __half* __restrict__ B,
             const float* __restrict__ bias, float* __restrict__ C,
             const float* __restrict__ rc, const float* __restrict__ rs,
             int M, int N, int K)
{
    extern __shared__ char sm[];
    const uint32_t sbase = smem_u32(sm);

    const int tid = threadIdx.x;
    const int wid = tid >> 5;
    const int lane = tid & 31;
    const int warpM = wid >> 1;
    const int warpN = wid & 1;
    const int bn = blockIdx.x * 128;
    const int bm = blockIdx.y * 128;

    float acc[4][8][4];
#pragma unroll
    for (int mi = 0; mi < 4; mi++)
#pragma unroll
        for (int ni = 0; ni < 8; ni++)
#pragma unroll
            for (int r = 0; r < 4; r++) acc[mi][ni][r] = 0.f;

    const int NI = K / TK;

    gemm_load_stage(sbase,         Ahi, Alo, B, bm, bn, 0,  K, tid);
    CP_COMMIT();
    gemm_load_stage(sbase + STAGE, Ahi, Alo, B, bm, bn, TK, K, tid);
    CP_COMMIT();

    int buf = 0;
    for (int i = 0; i < NI; i++) {
        if (i + 1 < NI) { CP_WAIT(1); } else { CP_WAIT(0); }
        __syncthreads();

        if (i + 2 < NI) {
            int nb = buf + 2; if (nb >= 3) nb -= 3;
            gemm_load_stage(sbase + nb * STAGE, Ahi, Alo, B, bm, bn,
                            (i + 2) * TK, K, tid);
            CP_COMMIT();
        }

        const uint32_t st = sbase + buf * STAGE;
        const uint32_t Ah = st, Al = st + TILE_B, Bh = st + 2 * TILE_B;
        const int ar = warpM * 64 + (lane & 15);
        const int br = warpN * 64 + (lane & 15);

#pragma unroll
        for (int ks = 0; ks < 2; ks++) {
            const int cc = ks * 2 + (lane >> 4);
            const uint32_t aoff = sw_off(ar, cc);
            const uint32_t boff = sw_off(br, cc);

            uint32_t ahf[4][4], alf[4][4];
#pragma unroll
            for (int mi = 0; mi < 4; mi++) {
                ldsm_x4(ahf[mi], Ah + aoff + mi * 1024);
                ldsm_x4(alf[mi], Al + aoff + mi * 1024);
            }
#pragma unroll
            for (int np = 0; np < 4; np++) {
                uint32_t bhf[4];
                ldsm_x4(bhf, Bh + boff + np * 1024);
#pragma unroll
                for (int mi = 0; mi < 4; mi++)
#pragma unroll
                    for (int o = 0; o < 2; o++) {
                        const int ni = np * 2 + o;
                        mma_f16(acc[mi][ni], ahf[mi], bhf[o], bhf[o + 2]);
                        mma_f16(acc[mi][ni], alf[mi], bhf[o], bhf[o + 2]);
                    }
            }
        }
        buf++; if (buf >= 3) buf = 0;
    }

    if (MODE == 0) {
#pragma unroll
        for (int mi = 0; mi < 4; mi++) {
            const int r0 = bm + warpM * 64 + mi * 16 + (lane >> 2);
#pragma unroll
            for (int ni = 0; ni < 8; ni++) {
                const int c0 = bn + warpN * 64 + ni * 8 + (lane & 3) * 2;
                const float b0 = bias[c0], b1 = bias[c0 + 1];
                float2 v0 = make_float2(acc[mi][ni][0] + b0, acc[mi][ni][1] + b1);
                float2 v1 = make_float2(acc[mi][ni][2] + b0, acc[mi][ni][3] + b1);
                *(float2*)(C + (size_t)r0 * N + c0) = v0;
                *(float2*)(C + (size_t)(r0 + 8) * N + c0) = v1;
            }
        }
    } else {
        const int region = bn >> 11;               // 0=Q, 1=K, 2=V
        const int h = (bn >> 7) & (NH - 1);
#pragma unroll
        for (int mi = 0; mi < 4; mi++) {
            const int r0 = bm + warpM * 64 + mi * 16 + (lane >> 2);
            const int bb = r0 >> 11;
            const int s0 = r0 & (SEQ - 1);
            const int s1 = s0 + 8;
            const size_t bhs0 = ((size_t)(bb * NH + h) * SEQ + s0) * DH;
            const size_t bhs1 = bhs0 + (size_t)8 * DH;
#pragma unroll
            for (int ni = 0; ni < 8; ni++) {
                const int c = warpN * 64 + ni * 8 + (lane & 3) * 2;
                const float bi0 = bias[bn + c], bi1 = bias[bn + c + 1];
                const float e0 = acc[mi][ni][0] + bi0, o0 = acc[mi][ni][1] + bi1;
                const float e1 = acc[mi][ni][2] + bi0, o1 = acc[mi][ni][3] + bi1;
                const size_t i0 = (bhs0 + c) >> 1;
                const size_t i1 = (bhs1 + c) >> 1;
                if (region == 2) {
                    ((uint32_t*)g_v)[i0] = pack_f16(e0, o0);
                    ((uint32_t*)g_v)[i1] = pack_f16(e1, o1);
                } else {
                    const int j = c >> 1;
                    const float c0 = rc[s0 * RH + j], sn0 = rs[s0 * RH + j];
                    const float c1 = rc[s1 * RH + j], sn1 = rs[s1 * RH + j];
                    const float re0 = e0 * c0 - o0 * sn0, ro0 = e0 * sn0 + o0 * c0;
                    const float re1 = e1 * c1 - o1 * sn1, ro1 = e1 * sn1 + o1 * c1;
                    if (region == 0) {
                        uint32_t hi, lo;
                        pack_hilo(re0, ro0, hi, lo);
                        ((uint32_t*)g_qhi)[i0] = hi; ((uint32_t*)g_qlo)[i0] = lo;
                        pack_hilo(re1, ro1, hi, lo);
                        ((uint32_t*)g_qhi)[i1] = hi; ((uint32_t*)g_qlo)[i1] = lo;
                    } else {
                        ((uint32_t*)g_k)[i0] = pack_f16(re0, ro0);
                        ((uint32_t*)g_k)[i1] = pack_f16(re1, ro1);
                    }
                }
            }
        }
    }
}

// ---------------- fp16x2 HMMA flash attention, Q-tile 64, Q/KV smem aliased --
// Q is staged in KV stage-0's buffer, fragments extracted to registers, then
// the buffer is recycled for the KV pipeline.  smem = 2*ASTAGE = 71.7KB ->
// 3 CTAs/SM (12 warps/SM) for latency hiding across softmax phases.
#define KSTR 272                 // 128 fp16 = 256B + 16 pad
#define VSTR 144                 // 64 fp16 = 128B + 16 pad
#define KTILE (64*KSTR)          // 17408
#define VTILE (128*VSTR)         // 18432
#define ASTAGE (KTILE + VTILE)   // 35840
#define QSTR 272
#define QTILE (64*QSTR)          // 17408 (2*QTILE = 34816 <= ASTAGE)
#define ATTN_SMEM (2*ASTAGE)     // 71680 -> 3 CTAs/SM

__device__ __forceinline__ void attn_load_kv(uint32_t st, int bh, int k0, int tid)
{
    {
        const int rb = tid >> 4, c = tid & 15;
#pragma unroll
        for (int q = 0; q < 8; q++) {
            const int r = q * 8 + rb;
            CP_ASYNC16(st + r * KSTR + c * 16,
                       g_k + ((size_t)bh * SEQ + k0 + r) * DH + c * 8);
        }
    }
    {
        const int rb = tid >> 3, c = tid & 7;
#pragma unroll
        for (int q = 0; q < 8; q++) {
            const int r = q * 16 + rb;
            CP_ASYNC16(st + KTILE + r * VSTR + c * 16,
                       g_vt + ((size_t)bh * DH + r) * SEQ + k0 + c * 8);
        }
    }
}

__global__ __launch_bounds__(128)
void attn_hmma()
{
    extern __shared__ char sm[];
    const uint32_t sbase = smem_u32(sm);
    const uint32_t qb_smem = sbase;          // aliased with KV stage 0
    const uint32_t stage0 = sbase;

    const int qb = 31 - blockIdx.x;           // heavy tiles first
    const int h = blockIdx.y, b = blockIdx.z;
    const int bh = b * NH + h;
    const int q0 = qb * 64;
    const int tid = threadIdx.x;
    const int w = tid >> 5;
    const int lane = tid & 31;
    const float scale = 0.08838834764831845f;

    // stage Q hi/lo into (future) KV stage-0 buffer
    {
        const int rb = tid >> 4, c = tid & 15;
#pragma unroll
        for (int sec = 0; sec < 2; sec++)
#pragma unroll
            for (int q = 0; q < 8; q++) {
                const int r = q * 8 + rb;
                const size_t g = ((size_t)bh * SEQ + q0 + r) * DH + c * 8;
                CP_ASYNC16(qb_smem + sec * QTILE + r * QSTR + c * 16,
                           (sec ? g_qlo : g_qhi) + g);
            }
    }
    CP_COMMIT();
    CP_WAIT(0);
    __syncthreads();

    uint32_t qh[8][4], ql[8][4];
    {
        const uint32_t arow = (w * 16 + (lane & 15)) * QSTR + (lane >> 4) * 16;
#pragma unroll
        for (int kt = 0; kt < 8; kt++) {
            ldsm_x4(qh[kt], qb_smem + arow + kt * 32);
            ldsm_x4(ql[kt], qb_smem + QTILE + arow + kt * 32);
        }
    }
    __syncthreads();   // all Q reads complete before stage0 is overwritten by KV

    float oa[16][4];
#pragma unroll
    for (int dt = 0; dt < 16; dt++)
#pragma unroll
        for (int r = 0; r < 4; r++) oa[dt][r] = 0.f;
    float m0 = -1e30f, m1 = -1e30f, l0 = 0.f, l1 = 0.f;

    const int nch = qb + 1;

    attn_load_kv(stage0, bh, 0, tid);
    CP_COMMIT();

    for (int kb = 0; kb < nch; kb++) {
        if (kb + 1 < nch) {
            attn_load_kv(sbase + ((kb + 1) & 1) * ASTAGE, bh, (kb + 1) * 64, tid);
            CP_COMMIT();
            CP_WAIT(1);
        } else {
            CP_WAIT(0);
        }
        __syncthreads();

        const uint32_t st = sbase + (kb & 1) * ASTAGE;
        const int k0 = kb * 64;

        float e[8][4];
#pragma unroll
        for (int nt = 0; nt < 8; nt++)
#pragma unroll
            for (int r = 0; r < 4; r++) e[nt][r] = 0.f;

#pragma unroll
        for (int kt = 0; kt < 8; kt++) {
            const uint32_t ko = kt * 32 + (lane >> 4) * 16;
#pragma unroll
            for (int np = 0; np < 4; np++) {
                const uint32_t brow = (np * 16 + (lane & 15)) * KSTR + ko;
                uint32_t bhf[4];
                ldsm_x4(bhf, st + brow);
#pragma unroll
                for (int o = 0; o < 2; o++) {
                    const int nt = 2 * np + o;
                    mma_f16(e[nt], qh[kt], bhf[o], bhf[o + 2]);
                    mma_f16(e[nt], ql[kt], bhf[o], bhf[o + 2]);
                }
            }
        }

#pragma unroll
        for (int nt = 0; nt < 8; nt++)
#pragma unroll
            for (int r = 0; r < 4; r++) e[nt][r] *= scale;

        const int row0 = q0 + w * 16 + (lane >> 2);
        if (kb == qb) {
#pragma unroll
            for (int nt = 0; nt < 8; nt++) {
                const int col = k0 + nt * 8 + (lane & 3) * 2;
                if (col     > row0)     e[nt][0] = -1e30f;
                if (col + 1 > row0)     e[nt][1] = -1e30f;
                if (col     > row0 + 8) e[nt][2] = -1e30f;
                if (col + 1 > row0 + 8) e[nt][3] = -1e30f;
            }
        }

        float rm0 = e[0][0], rm1 = e[0][2];
#pragma unroll
        for (int nt = 0; nt < 8; nt++) {
            rm0 = fmaxf(rm0, fmaxf(e[nt][0], e[nt][1]));
            rm1 = fmaxf(rm1, fmaxf(e[nt][2], e[nt][3]));
        }
        rm0 = fmaxf(rm0, __shfl_xor_sync(0xffffffffu, rm0, 1));
        rm0 = fmaxf(rm0, __shfl_xor_sync(0xffffffffu, rm0, 2));
        rm1 = fmaxf(rm1, __shfl_xor_sync(0xffffffffu, rm1, 1));
        rm1 = fmaxf(rm1, __shfl_xor_sync(0xffffffffu, rm1, 2));

        const float mn0 = fmaxf(m0, rm0), mn1 = fmaxf(m1, rm1);
        const float al0 = __expf(m0 - mn0), al1 = __expf(m1 - mn1);
        m0 = mn0; m1 = mn1;

        float s0 = 0.f, s1 = 0.f;
#pragma unroll
        for (int nt = 0; nt < 8; nt++) {
            e[nt][0] = __expf(e[nt][0] - mn0);
            e[nt][1] = __expf(e[nt][1] - mn0);
            e[nt][2] = __expf(e[nt][2] - mn1);
            e[nt][3] = __expf(e[nt][3] - mn1);
            s0 += e[nt][0] + e[nt][1];
            s1 += e[nt][2] + e[nt][3];
        }
        s0 += __shfl_xor_sync(0xffffffffu, s0, 1);
        s0 += __shfl_xor_sync(0xffffffffu, s0, 2);
        s1 += __shfl_xor_sync(0xffffffffu, s1, 1);
        s1 += __shfl_xor_sync(0xffffffffu, s1, 2);
        l0 = l0 * al0 + s0;
        l1 = l1 * al1 + s1;

#pragma unroll
        for (int dt = 0; dt < 16; dt++) {
            oa[dt][0] *= al0; oa[dt][1] *= al0;
            oa[dt][2] *= al1; oa[dt][3] *= al1;
        }

        const uint32_t vb = st + KTILE;
#pragma unroll
        for (int kt2 = 0; kt2 < 4; kt2++) {
            const int ta = 2 * kt2, tb = ta + 1;
            uint32_t ph[4], pl[4];
            pack_hilo(e[ta][0], e[ta][1], ph[0], pl[0]);
            pack_hilo(e[ta][2], e[ta][3], ph[1], pl[1]);
            pack_hilo(e[tb][0], e[tb][1], ph[2], pl[2]);
            pack_hilo(e[tb][2], e[tb][3], ph[3], pl[3]);

            const uint32_t ko = kt2 * 32 + (lane >> 4) * 16;
#pragma unroll
            for (int np = 0; np < 8; np++) {
                const uint32_t brow = (np * 16 + (lane & 15)) * VSTR + ko;
                uint32_t bhf[4];
                ldsm_x4(bhf, vb + brow);
#pragma unroll
                for (int o = 0; o < 2; o++) {
                    const int dt = 2 * np + o;
                    mma_f16(oa[dt], ph, bhf[o], bhf[o + 2]);
                    mma_f16(oa[dt], pl, bhf[o], bhf[o + 2]);
                }
            }
        }
        __syncthreads();
    }

    const float inv0 = 1.f / l0, inv1 = 1.f / l1;
    const size_t tokA = (size_t)b * SEQ + q0 + w * 16 + (lane >> 2);
    const size_t tokB = tokA + 8;
    const int colb = h * DH + (lane & 3) * 2;
    uint32_t* ahi = (uint32_t*)g_ahi;
    uint32_t* alo = (uint32_t*)g_alo;
#pragma unroll
    for (int dt = 0; dt < 16; dt++) {
        const int col = colb + dt * 8;
        uint32_t hi, lo;
        pack_hilo(oa[dt][0] * inv0, oa[dt][1] * inv0, hi, lo);
        ahi[(tokA * DM + col) >> 1] = hi;
        alo[(tokA * DM + col) >> 1] = lo;
        pack_hilo(oa[dt][2] * inv1, oa[dt][3] * inv1, hi, lo);
        ahi[(tokB * DM + col) >> 1] = hi;
        alo[(tokB * DM + col) >> 1] = lo;
    }
}

// ---------------- launch -----------------------------------------------------
extern "C" void kernel_launch(void* const* d_in, const int* in_sizes, int n_in,
                              void* d_out, int out_size)
{
    const float* x     = (const float*)d_in[0];
    const float* w_qkv = (const float*)d_in[1];
    const float* b_qkv = (const float*)d_in[2];
    const float* w_out = (const float*)d_in[3];
    const float* b_out = (const float*)d_in[4];
    const float* rc    = (const float*)d_in[5];
    const float* rs    = (const float*)d_in[6];
    float* out = (float*)d_out;

    __half *p_xhi, *p_xlo, *p_ahi, *p_alo, *p_wq, *p_wo;
    cudaGetSymbolAddress((void**)&p_xhi, g_xhi);
    cudaGetSymbolAddress((void**)&p_xlo, g_xlo);
    cudaGetSymbolAddress((void**)&p_ahi, g_ahi);
    cudaGetSymbolAddress((void**)&p_alo, g_alo);
    cudaGetSymbolAddress((void**)&p_wq, g_wqkvT);
    cudaGetSymbolAddress((void**)&p_wo, g_woutT);

    cudaFuncSetAttribute(gemm_tc<0>,
                         cudaFuncAttributeMaxDynamicSharedMemorySize, GEMM_SMEM);
    cudaFuncSetAttribute(gemm_tc<1>,
                         cudaFuncAttributeMaxDynamicSharedMemorySize, GEMM_SMEM);
    cudaFuncSetAttribute(attn_hmma,
                         cudaFuncAttributeMaxDynamicSharedMemorySize, ATTN_SMEM);

    // 1) split x -> fp16 hi/lo
    {
        int n4 = NTOK * DM / 4;
        split_a<<<(n4 + 255) / 256, 256>>>(x, p_xhi, p_xlo, n4);
    }
    // 2) transpose weights -> fp16
    transpose_w<<<dim3(QKVN / 32, DM / 32), dim3(32, 8)>>>(w_qkv, p_wq, DM, QKVN);
    transpose_w<<<dim3(DM / 32, DM / 32), dim3(32, 8)>>>(w_out, p_wo, DM, DM);
    // 3) fused QKV GEMM + bias + RoPE + fp16 split -> g_qhi/qlo, g_k, g_v
    gemm_tc<1><<<dim3(QKVN / 128, NTOK / 128), 128, GEMM_SMEM>>>(
        p_xhi, p_xlo, p_wq, b_qkv, nullptr, rc, rs, NTOK, QKVN, DM);
    // 4) V transpose (fp16 in/out) -> [bh,d,s]
    v_transpose_f16<<<dim3(DH / 32, SEQ / 32, BH), dim3(32, 8)>>>();
    // 5) fp16x2 HMMA flash attention, Q/KV aliased smem, 3 CTAs/SM
    attn_hmma<<<dim3(SEQ / 64, NH, BATCH), 128, ATTN_SMEM>>>();
    // 6) out = att @ w_out + b  (fp16x2 HMMA)
    gemm_tc<0><<<dim3(DM / 128, NTOK / 128), 128, GEMM_SMEM>>>(
        p_ahi, p_alo, p_wo, b_out, out, nullptr, nullptr, NTOK, DM, DM);
}